// round 1
// baseline (speedup 1.0000x reference)
#include <cuda_runtime.h>
#include <math.h>

// Problem constants
#define Bn  2
#define Tn  2048
#define En  1024
#define NHn 16
#define HSn 64
#define Mn  (Bn * Tn)        // 4096 rows for projections

// ---------------- scratch (device globals; no allocation) ----------------
__device__ float g_Q[(size_t)Bn * NHn * Tn * HSn];   // [b,h,t,d]
__device__ float g_K[(size_t)Bn * NHn * Tn * HSn];
__device__ float g_V[(size_t)Bn * NHn * Tn * HSn];
__device__ float g_A[(size_t)Bn * Tn * En];          // [b,t,h*d] == [b,t,e]

// =====================================================================
// Tiled SGEMM core: C[128x128] = X[128xK] * W^T (W is [N,K], both K-major)
// 256 threads, 8x8 micro-tile per thread, BK=16.
// =====================================================================
__device__ __forceinline__ void gemm_compute(const float* __restrict__ X,
                                             const float* __restrict__ W,
                                             float (&acc)[8][8])
{
    __shared__ float Xs[16][132];   // [k][m], pad 4 -> bank-friendly
    __shared__ float Ws[16][132];   // [k][n]

    const int tid = threadIdx.x;
    const int tx  = tid & 15;       // 0..15 (cols)
    const int ty  = tid >> 4;       // 0..15 (rows)
    const int rowBase = blockIdx.y * 128;
    const int colBase = blockIdx.x * 128;

    const int lrow = tid >> 2;          // 0..63
    const int lk4  = (tid & 3) * 4;     // 0,4,8,12

    for (int k0 = 0; k0 < En; k0 += 16) {
        #pragma unroll
        for (int s = 0; s < 2; s++) {
            const int r = lrow + s * 64;
            float4 v = *(const float4*)&X[(size_t)(rowBase + r) * En + k0 + lk4];
            Xs[lk4 + 0][r] = v.x; Xs[lk4 + 1][r] = v.y;
            Xs[lk4 + 2][r] = v.z; Xs[lk4 + 3][r] = v.w;
            float4 w = *(const float4*)&W[(size_t)(colBase + r) * En + k0 + lk4];
            Ws[lk4 + 0][r] = w.x; Ws[lk4 + 1][r] = w.y;
            Ws[lk4 + 2][r] = w.z; Ws[lk4 + 3][r] = w.w;
        }
        __syncthreads();

        #pragma unroll
        for (int kk = 0; kk < 16; kk++) {
            float a[8], b[8];
            *(float4*)&a[0] = *(const float4*)&Xs[kk][ty * 8];
            *(float4*)&a[4] = *(const float4*)&Xs[kk][ty * 8 + 4];
            *(float4*)&b[0] = *(const float4*)&Ws[kk][tx * 4];
            *(float4*)&b[4] = *(const float4*)&Ws[kk][tx * 4 + 64];
            #pragma unroll
            for (int i = 0; i < 8; i++)
                #pragma unroll
                for (int j = 0; j < 8; j++)
                    acc[i][j] = fmaf(a[i], b[j], acc[i][j]);
        }
        __syncthreads();
    }
}

// ---------------- fused QKV projection, epilogue scatters to [b,h,t,d] ---
__global__ void __launch_bounds__(256) gemm_qkv_kernel(
    const float* __restrict__ X,
    const float* __restrict__ Wq, const float* __restrict__ Wk, const float* __restrict__ Wv,
    const float* __restrict__ bq, const float* __restrict__ bk, const float* __restrict__ bv)
{
    const float* W; const float* bias; float* out;
    if (blockIdx.z == 0)      { W = Wq; bias = bq; out = g_Q; }
    else if (blockIdx.z == 1) { W = Wk; bias = bk; out = g_K; }
    else                      { W = Wv; bias = bv; out = g_V; }

    float acc[8][8] = {};
    gemm_compute(X, W, acc);

    const int tx = threadIdx.x & 15, ty = threadIdx.x >> 4;
    const int rowBase = blockIdx.y * 128;
    const int c0 = blockIdx.x * 128 + tx * 4;
    const int c1 = c0 + 64;
    const float4 bb0 = *(const float4*)&bias[c0];
    const float4 bb1 = *(const float4*)&bias[c1];
    const int h0 = c0 >> 6, d0 = c0 & 63;
    const int h1 = c1 >> 6;

    #pragma unroll
    for (int i = 0; i < 8; i++) {
        const int row = rowBase + ty * 8 + i;
        const int b = row >> 11;          // row / T
        const int t = row & (Tn - 1);
        float4 o0 = make_float4(acc[i][0] + bb0.x, acc[i][1] + bb0.y,
                                acc[i][2] + bb0.z, acc[i][3] + bb0.w);
        float4 o1 = make_float4(acc[i][4] + bb1.x, acc[i][5] + bb1.y,
                                acc[i][6] + bb1.z, acc[i][7] + bb1.w);
        *(float4*)&out[(((size_t)(b * NHn + h0)) * Tn + t) * HSn + d0] = o0;
        *(float4*)&out[(((size_t)(b * NHn + h1)) * Tn + t) * HSn + d0] = o1;
    }
}

// ---------------- output projection: out = A @ Wo^T + bo -----------------
__global__ void __launch_bounds__(256) gemm_out_kernel(
    const float* __restrict__ Wo, const float* __restrict__ bo,
    float* __restrict__ out)
{
    float acc[8][8] = {};
    gemm_compute(g_A, Wo, acc);

    const int tx = threadIdx.x & 15, ty = threadIdx.x >> 4;
    const int rowBase = blockIdx.y * 128;
    const int c0 = blockIdx.x * 128 + tx * 4;
    const int c1 = c0 + 64;
    const float4 bb0 = *(const float4*)&bo[c0];
    const float4 bb1 = *(const float4*)&bo[c1];

    #pragma unroll
    for (int i = 0; i < 8; i++) {
        const int row = rowBase + ty * 8 + i;
        float4 o0 = make_float4(acc[i][0] + bb0.x, acc[i][1] + bb0.y,
                                acc[i][2] + bb0.z, acc[i][3] + bb0.w);
        float4 o1 = make_float4(acc[i][4] + bb1.x, acc[i][5] + bb1.y,
                                acc[i][6] + bb1.z, acc[i][7] + bb1.w);
        *(float4*)&out[(size_t)row * En + c0] = o0;
        *(float4*)&out[(size_t)row * En + c1] = o1;
    }
}

// =====================================================================
// Flash attention, causal. Br=Bc=64, 256 threads, 4x4 per thread.
// Smem (dynamic, 69632B): Qt[d][r], Kt[d][c], Vs[c][d], Pt[c][r], stride 68.
// =====================================================================
#define FL_LD   68
#define FL_SMEM (4 * 64 * FL_LD * 4)

__global__ void __launch_bounds__(256) flash_attn_kernel()
{
    extern __shared__ float sm[];
    float* Qt = sm;
    float* Kt = sm + 64 * FL_LD;
    float* Vs = sm + 2 * 64 * FL_LD;
    float* Pt = sm + 3 * 64 * FL_LD;

    const int qt  = blockIdx.x;            // q tile: 0..31
    const int bh  = blockIdx.y;            // b*NH + h: 0..31
    const int tid = threadIdx.x;
    const int tx  = tid & 15;
    const int ty  = tid >> 4;
    const int qbase = qt * 64;

    const float* Qg = g_Q + (size_t)bh * Tn * HSn;
    const float* Kg = g_K + (size_t)bh * Tn * HSn;
    const float* Vg = g_V + (size_t)bh * Tn * HSn;

    // load Q tile transposed, pre-scaled by 1/sqrt(HS)
    #pragma unroll
    for (int s = 0; s < 4; s++) {
        const int idx = tid + s * 256;
        const int r = idx >> 4;
        const int d4 = (idx & 15) * 4;
        float4 v = *(const float4*)&Qg[(size_t)(qbase + r) * HSn + d4];
        Qt[(d4 + 0) * FL_LD + r] = v.x * 0.125f;
        Qt[(d4 + 1) * FL_LD + r] = v.y * 0.125f;
        Qt[(d4 + 2) * FL_LD + r] = v.z * 0.125f;
        Qt[(d4 + 3) * FL_LD + r] = v.w * 0.125f;
    }

    float m[4], l[4], O[4][4];
    #pragma unroll
    for (int i = 0; i < 4; i++) {
        m[i] = -1e30f; l[i] = 0.f;
        #pragma unroll
        for (int j = 0; j < 4; j++) O[i][j] = 0.f;
    }

    for (int kt = 0; kt <= qt; kt++) {
        const int kbase = kt * 64;
        __syncthreads();  // prev iter's Kt/Vs/Pt reads done (also covers Q load)

        #pragma unroll
        for (int s = 0; s < 4; s++) {
            const int idx = tid + s * 256;
            const int r = idx >> 4;
            const int d4 = (idx & 15) * 4;
            float4 kv = *(const float4*)&Kg[(size_t)(kbase + r) * HSn + d4];
            Kt[(d4 + 0) * FL_LD + r] = kv.x;
            Kt[(d4 + 1) * FL_LD + r] = kv.y;
            Kt[(d4 + 2) * FL_LD + r] = kv.z;
            Kt[(d4 + 3) * FL_LD + r] = kv.w;
            float4 vv = *(const float4*)&Vg[(size_t)(kbase + r) * HSn + d4];
            *(float4*)&Vs[r * FL_LD + d4] = vv;
        }
        __syncthreads();

        // S = (Q * scale) @ K^T  (4x4 per thread)
        float S[4][4] = {};
        #pragma unroll 8
        for (int kk = 0; kk < 64; kk++) {
            float a[4], b[4];
            *(float4*)a = *(const float4*)&Qt[kk * FL_LD + ty * 4];
            *(float4*)b = *(const float4*)&Kt[kk * FL_LD + tx * 4];
            #pragma unroll
            for (int i = 0; i < 4; i++)
                #pragma unroll
                for (int j = 0; j < 4; j++)
                    S[i][j] = fmaf(a[i], b[j], S[i][j]);
        }

        if (kt == qt) {   // diagonal tile: causal mask
            #pragma unroll
            for (int i = 0; i < 4; i++)
                #pragma unroll
                for (int j = 0; j < 4; j++)
                    if (tx * 4 + j > ty * 4 + i) S[i][j] = -1e30f;
        }

        // row max across the 16 tx lanes (lane bits 0..3 == tx)
        float rm[4];
        #pragma unroll
        for (int i = 0; i < 4; i++)
            rm[i] = fmaxf(fmaxf(S[i][0], S[i][1]), fmaxf(S[i][2], S[i][3]));
        #pragma unroll
        for (int off = 1; off < 16; off <<= 1)
            #pragma unroll
            for (int i = 0; i < 4; i++)
                rm[i] = fmaxf(rm[i], __shfl_xor_sync(0xffffffffu, rm[i], off));

        float rs[4], alpha[4];
        #pragma unroll
        for (int i = 0; i < 4; i++) {
            const float mn = fmaxf(m[i], rm[i]);
            alpha[i] = __expf(m[i] - mn);
            m[i] = mn;
            float s0 = 0.f;
            #pragma unroll
            for (int j = 0; j < 4; j++) {
                S[i][j] = __expf(S[i][j] - mn);
                s0 += S[i][j];
            }
            rs[i] = s0;
        }
        #pragma unroll
        for (int off = 1; off < 16; off <<= 1)
            #pragma unroll
            for (int i = 0; i < 4; i++)
                rs[i] += __shfl_xor_sync(0xffffffffu, rs[i], off);
        #pragma unroll
        for (int i = 0; i < 4; i++) {
            l[i] = l[i] * alpha[i] + rs[i];
            #pragma unroll
            for (int j = 0; j < 4; j++) O[i][j] *= alpha[i];
        }

        // P (transposed: [key][qrow])
        #pragma unroll
        for (int j = 0; j < 4; j++)
            #pragma unroll
            for (int i = 0; i < 4; i++)
                Pt[(tx * 4 + j) * FL_LD + ty * 4 + i] = S[i][j];
        __syncthreads();

        // O += P @ V
        #pragma unroll 8
        for (int j = 0; j < 64; j++) {
            float p[4], v[4];
            *(float4*)p = *(const float4*)&Pt[j * FL_LD + ty * 4];
            *(float4*)v = *(const float4*)&Vs[j * FL_LD + tx * 4];
            #pragma unroll
            for (int i = 0; i < 4; i++)
                #pragma unroll
                for (int jj = 0; jj < 4; jj++)
                    O[i][jj] = fmaf(p[i], v[jj], O[i][jj]);
        }
    }

    // normalize and write to A in [b,t,h,d]
    const int b = bh >> 4, h = bh & 15;
    #pragma unroll
    for (int i = 0; i < 4; i++) {
        const float inv = 1.0f / l[i];
        const int q = qbase + ty * 4 + i;
        float4 o = make_float4(O[i][0] * inv, O[i][1] * inv,
                               O[i][2] * inv, O[i][3] * inv);
        *(float4*)&g_A[(((size_t)b * Tn + q) * NHn + h) * HSn + tx * 4] = o;
    }
}

// =====================================================================
extern "C" void kernel_launch(void* const* d_in, const int* in_sizes, int n_in,
                              void* d_out, int out_size)
{
    (void)in_sizes; (void)n_in; (void)out_size;
    const float* X  = (const float*)d_in[0];
    const float* Wq = (const float*)d_in[1];
    const float* bq = (const float*)d_in[2];
    const float* Wk = (const float*)d_in[3];
    const float* bk = (const float*)d_in[4];
    const float* Wv = (const float*)d_in[5];
    const float* bv = (const float*)d_in[6];
    const float* Wo = (const float*)d_in[7];
    const float* bo = (const float*)d_in[8];
    float* out = (float*)d_out;

    cudaFuncSetAttribute(flash_attn_kernel,
                         cudaFuncAttributeMaxDynamicSharedMemorySize, FL_SMEM);

    dim3 blk(256);
    gemm_qkv_kernel<<<dim3(En / 128, Mn / 128, 3), blk>>>(X, Wq, Wk, Wv, bq, bk, bv);
    flash_attn_kernel<<<dim3(Tn / 64, Bn * NHn), blk, FL_SMEM>>>();
    gemm_out_kernel<<<dim3(En / 128, Mn / 128), blk>>>(Wo, bo, out);
}

// round 3
// speedup vs baseline: 2.4555x; 2.4555x over previous
#include <cuda_runtime.h>
#include <cuda_bf16.h>
#include <cstdint>

// Problem constants
#define Bn  2
#define Tn  2048
#define En  1024
#define NHn 16
#define HSn 64
#define Mn  (Bn * Tn)        // 4096 token rows

// ---------------- scratch (device globals; no allocation) ----------------
__device__ __nv_bfloat16 g_Xh[(size_t)Mn * En];
__device__ __nv_bfloat16 g_Xl[(size_t)Mn * En];
__device__ __nv_bfloat16 g_Wqh[(size_t)En * En];
__device__ __nv_bfloat16 g_Wql[(size_t)En * En];
__device__ __nv_bfloat16 g_Wkh[(size_t)En * En];
__device__ __nv_bfloat16 g_Wkl[(size_t)En * En];
__device__ __nv_bfloat16 g_Wvh[(size_t)En * En];
__device__ __nv_bfloat16 g_Wvl[(size_t)En * En];
__device__ __nv_bfloat16 g_Woh[(size_t)En * En];
__device__ __nv_bfloat16 g_Wol[(size_t)En * En];
__device__ __nv_bfloat16 g_Qh[(size_t)Mn * En];
__device__ __nv_bfloat16 g_Ql[(size_t)Mn * En];
__device__ __nv_bfloat16 g_Kh[(size_t)Mn * En];
__device__ __nv_bfloat16 g_Kl[(size_t)Mn * En];
__device__ __nv_bfloat16 g_Vh[(size_t)Mn * En];
__device__ __nv_bfloat16 g_Vl[(size_t)Mn * En];
__device__ __nv_bfloat16 g_Ah[(size_t)Mn * En];
__device__ __nv_bfloat16 g_Al[(size_t)Mn * En];

// =====================================================================
// Baseline-PTX helpers (valid on compute_103 virtual arch)
// =====================================================================
__device__ __forceinline__ uint32_t smem_u32(const void* p) {
    uint32_t a;
    asm("{ .reg .u64 t; cvta.to.shared.u64 t, %1; cvt.u32.u64 %0, t; }"
        : "=r"(a) : "l"(p));
    return a;
}

__device__ __forceinline__ void mma_bf16(float* d, const uint32_t* a,
                                         const uint32_t* b) {
    asm volatile(
        "mma.sync.aligned.m16n8k16.row.col.f32.bf16.bf16.f32 "
        "{%0,%1,%2,%3}, {%4,%5,%6,%7}, {%8,%9}, {%0,%1,%2,%3};\n"
        : "+f"(d[0]), "+f"(d[1]), "+f"(d[2]), "+f"(d[3])
        : "r"(a[0]), "r"(a[1]), "r"(a[2]), "r"(a[3]), "r"(b[0]), "r"(b[1]));
}

__device__ __forceinline__ void ldsm_x4(uint32_t* r, uint32_t a) {
    asm volatile("ldmatrix.sync.aligned.m8n8.x4.shared.b16 {%0,%1,%2,%3}, [%4];"
                 : "=r"(r[0]), "=r"(r[1]), "=r"(r[2]), "=r"(r[3]) : "r"(a));
}
__device__ __forceinline__ void ldsm_x4_t(uint32_t* r, uint32_t a) {
    asm volatile("ldmatrix.sync.aligned.m8n8.x4.trans.shared.b16 {%0,%1,%2,%3}, [%4];"
                 : "=r"(r[0]), "=r"(r[1]), "=r"(r[2]), "=r"(r[3]) : "r"(a));
}

__device__ __forceinline__ void cp16(uint32_t d, const void* g) {
    asm volatile("cp.async.cg.shared.global [%0], [%1], 16;" :: "r"(d), "l"(g));
}
#define CP_COMMIT() asm volatile("cp.async.commit_group;" ::: "memory")
#define CP_WAIT0()  asm volatile("cp.async.wait_group 0;" ::: "memory")
#define CP_WAIT1()  asm volatile("cp.async.wait_group 1;" ::: "memory")

__device__ __forceinline__ uint32_t packbf(float a, float b) {
    __nv_bfloat162 t = __floats2bfloat162_rn(a, b);   // .x = a -> low bits
    return *reinterpret_cast<uint32_t*>(&t);
}

// ---- tcgen05 build-capability probe: NEVER launched. If this round builds,
// the compute_103 PTX pass tolerated the guard; next round check whether an
// sm_103a SASS pass also exists (probe kernel present in cubin/SASS dump).
#if defined(__CUDA_ARCH_FEAT_SM103_ALL) || defined(__CUDA_ARCH_FEAT_SM100_ALL)
#define TCGEN05_OK 1
#endif
__global__ void tcg_probe_kernel(uint32_t* out) {
#ifdef TCGEN05_OK
    __shared__ uint32_t sptr[32];
    uint32_t sa = smem_u32(sptr);
    if (threadIdx.x < 32) {
        asm volatile("tcgen05.alloc.cta_group::1.sync.aligned.shared::cta.b32 [%0], 32;"
                     :: "r"(sa) : "memory");
    }
    __syncthreads();
    uint32_t t = sptr[0];
    if (threadIdx.x < 32)
        asm volatile("tcgen05.dealloc.cta_group::1.sync.aligned.b32 %0, 32;" :: "r"(t));
    out[0] = t;
#else
    out[0] = 0xdead;
#endif
}

// =====================================================================
// split kernel: fp32 -> bf16 hi/lo pair into device globals
// =====================================================================
__global__ void split_kernel(const float* __restrict__ src, int which, int n)
{
    __nv_bfloat16 *hi, *lo;
    switch (which) {
        case 0: hi = g_Xh;  lo = g_Xl;  break;
        case 1: hi = g_Wqh; lo = g_Wql; break;
        case 2: hi = g_Wkh; lo = g_Wkl; break;
        case 3: hi = g_Wvh; lo = g_Wvl; break;
        default: hi = g_Woh; lo = g_Wol; break;
    }
    for (int i = blockIdx.x * blockDim.x + threadIdx.x; i < n;
         i += gridDim.x * blockDim.x) {
        float x = src[i];
        __nv_bfloat16 h = __float2bfloat16(x);
        hi[i] = h;
        lo[i] = __float2bfloat16(x - __bfloat162float(h));
    }
}

// =====================================================================
// GEMM: C[128x128] = A[4096xK] * W^T + bias, bf16x3 via mma.sync.
// 256 thr, 8 warps (4m x 2n), k-stage 32, cp.async double buffer.
// smem row = 32 bf16 data + 8 pad = 80B (ldmatrix conflict-free).
// =====================================================================
#define GTILE  (128 * 80)      // one [128 x 32] bf16 tile (padded)
#define GSTAGE (4 * GTILE)     // Ah, Al, Bh, Bl
#define GEMM_SMEM (2 * GSTAGE) // 81920

__device__ __forceinline__ void gemm_prefetch(
    uint32_t sbs, const __nv_bfloat16* pA0, const __nv_bfloat16* pA1,
    const __nv_bfloat16* pB0, const __nv_bfloat16* pB1, int k0, int tid)
{
    #pragma unroll
    for (int t = 0; t < 4; t++) {
        const __nv_bfloat16* s = (t == 0) ? pA0 : (t == 1) ? pA1
                               : (t == 2) ? pB0 : pB1;
        #pragma unroll
        for (int i = 0; i < 2; i++) {
            int cc  = i * 256 + tid;       // 0..511
            int row = cc >> 2, seg = cc & 3;
            cp16(sbs + t * GTILE + row * 80 + seg * 16,
                 s + (size_t)row * En + k0 + seg * 8);
        }
    }
}

__device__ __forceinline__ void gemm_core(
    const __nv_bfloat16* __restrict__ Ah, const __nv_bfloat16* __restrict__ Al,
    const __nv_bfloat16* __restrict__ Bh, const __nv_bfloat16* __restrict__ Bl,
    const float* __restrict__ bias, float* __restrict__ outF,
    __nv_bfloat16* __restrict__ outH, __nv_bfloat16* __restrict__ outL)
{
    extern __shared__ char smc[];
    const uint32_t sb = smem_u32(smc);
    const int tid = threadIdx.x, lane = tid & 31, wid = tid >> 5;
    const int wm = wid & 3, wn = wid >> 2;
    const int rowBase = blockIdx.y * 128, colBase = blockIdx.x * 128;

    const __nv_bfloat16* pA0 = Ah + (size_t)rowBase * En;
    const __nv_bfloat16* pA1 = Al + (size_t)rowBase * En;
    const __nv_bfloat16* pB0 = Bh + (size_t)colBase * En;
    const __nv_bfloat16* pB1 = Bl + (size_t)colBase * En;

    float acc[2][8][4];
    #pragma unroll
    for (int i = 0; i < 2; i++)
        #pragma unroll
        for (int j = 0; j < 8; j++)
            #pragma unroll
            for (int e = 0; e < 4; e++) acc[i][j][e] = 0.f;

    gemm_prefetch(sb, pA0, pA1, pB0, pB1, 0, tid);
    CP_COMMIT();

    const uint32_t aoff = (lane & 15) * 80 + (lane >> 4) * 16;
    const uint32_t boff = (((lane & 16) >> 1) + (lane & 7)) * 80
                        + ((lane & 8) ? 16 : 0);

    for (int st = 0; st < En / 32; st++) {
        if (st + 1 < En / 32) {
            gemm_prefetch(sb + ((st + 1) & 1) * GSTAGE,
                          pA0, pA1, pB0, pB1, (st + 1) * 32, tid);
            CP_COMMIT();
            CP_WAIT1();
        } else {
            CP_WAIT0();
        }
        __syncthreads();
        const uint32_t s0 = sb + (st & 1) * GSTAGE;
        const uint32_t aH = s0, aL = s0 + GTILE, bH = s0 + 2 * GTILE,
                       bL = s0 + 3 * GTILE;

        #pragma unroll
        for (int kk = 0; kk < 2; kk++) {
            uint32_t ah[2][4], al[2][4], bh4[4][4], bl4[4][4];
            #pragma unroll
            for (int mi = 0; mi < 2; mi++) {
                const uint32_t r = (wm * 32 + mi * 16) * 80 + aoff + kk * 32;
                ldsm_x4(ah[mi], aH + r);
                ldsm_x4(al[mi], aL + r);
            }
            #pragma unroll
            for (int n4 = 0; n4 < 4; n4++) {
                const uint32_t r = (wn * 64 + n4 * 16) * 80 + boff + kk * 32;
                ldsm_x4(bh4[n4], bH + r);
                ldsm_x4(bl4[n4], bL + r);
            }
            #pragma unroll
            for (int mi = 0; mi < 2; mi++)
                #pragma unroll
                for (int nj = 0; nj < 8; nj++) {
                    const uint32_t* bhp = &bh4[nj >> 1][(nj & 1) * 2];
                    const uint32_t* blp = &bl4[nj >> 1][(nj & 1) * 2];
                    mma_bf16(acc[mi][nj], ah[mi], bhp);
                    mma_bf16(acc[mi][nj], ah[mi], blp);
                    mma_bf16(acc[mi][nj], al[mi], bhp);
                }
        }
        __syncthreads();
    }

    // epilogue
    #pragma unroll
    for (int mi = 0; mi < 2; mi++) {
        const int rb = rowBase + wm * 32 + mi * 16 + (lane >> 2);
        #pragma unroll
        for (int half = 0; half < 2; half++) {
            const size_t r = (size_t)(rb + half * 8);
            #pragma unroll
            for (int nj = 0; nj < 8; nj++) {
                const int col = colBase + wn * 64 + nj * 8 + (lane & 3) * 2;
                float v0 = acc[mi][nj][half * 2 + 0] + bias[col];
                float v1 = acc[mi][nj][half * 2 + 1] + bias[col + 1];
                if (outF) {
                    *(float2*)&outF[r * En + col] = make_float2(v0, v1);
                } else {
                    __nv_bfloat16 h0 = __float2bfloat16(v0);
                    __nv_bfloat16 h1 = __float2bfloat16(v1);
                    *(uint32_t*)&outH[r * En + col] =
                        packbf(__bfloat162float(h0), __bfloat162float(h1));
                    *(uint32_t*)&outL[r * En + col] =
                        packbf(v0 - __bfloat162float(h0),
                               v1 - __bfloat162float(h1));
                }
            }
        }
    }
}

__global__ void __launch_bounds__(256) gemm_qkv(
    const float* bq, const float* bk, const float* bv)
{
    const __nv_bfloat16 *Wh, *Wl; const float* bias;
    __nv_bfloat16 *oh, *ol;
    if (blockIdx.z == 0)      { Wh = g_Wqh; Wl = g_Wql; bias = bq; oh = g_Qh; ol = g_Ql; }
    else if (blockIdx.z == 1) { Wh = g_Wkh; Wl = g_Wkl; bias = bk; oh = g_Kh; ol = g_Kl; }
    else                      { Wh = g_Wvh; Wl = g_Wvl; bias = bv; oh = g_Vh; ol = g_Vl; }
    gemm_core(g_Xh, g_Xl, Wh, Wl, bias, nullptr, oh, ol);
}

__global__ void __launch_bounds__(256) gemm_out(const float* bo, float* out)
{
    gemm_core(g_Ah, g_Al, g_Woh, g_Wol, bo, out, nullptr, nullptr);
}

// =====================================================================
// Flash attention (causal) via mma.sync bf16x3.
// CTA: 128 q rows x 64-key tiles, 256 thr, warp w owns rows w*16..+15.
// KV tiles (Kh,Kl,Vh,Vl) [64 x 64] bf16, smem row 64+8 pad = 144B.
// =====================================================================
#define KVTILE  (64 * 144)     // 9216
#define KVSTAGE (4 * KVTILE)   // 36864
#define FL_SMEM (2 * KVSTAGE)  // 73728

__device__ __forceinline__ void kv_prefetch(
    uint32_t sb, int buf, int kt2,
    const __nv_bfloat16* Kh, const __nv_bfloat16* Kl,
    const __nv_bfloat16* Vh, const __nv_bfloat16* Vl, int tid)
{
    const uint32_t s0 = sb + buf * KVSTAGE;
    const size_t rowoff = (size_t)kt2 * 64;
    #pragma unroll
    for (int t = 0; t < 4; t++) {
        const __nv_bfloat16* src = (t == 0) ? Kh : (t == 1) ? Kl
                                 : (t == 2) ? Vh : Vl;
        #pragma unroll
        for (int i = 0; i < 2; i++) {
            int cc  = i * 256 + tid;     // 0..511
            int row = cc >> 3, seg = cc & 7;
            cp16(s0 + t * KVTILE + row * 144 + seg * 16,
                 src + (rowoff + row) * En + seg * 8);
        }
    }
}

__global__ void __launch_bounds__(256) flash_mma()
{
    extern __shared__ char smc[];
    const uint32_t sb = smem_u32(smc);
    const int tid = threadIdx.x, lane = tid & 31, wp = tid >> 5;
    const int g = lane >> 2, tg = lane & 3;
    const int qt = (int)gridDim.x - 1 - (int)blockIdx.x;   // big tiles first
    const int bh = blockIdx.y, bb = bh >> 4, hh = bh & 15;

    const size_t headoff = (size_t)bb * Tn * En + hh * HSn;
    const __nv_bfloat16* Kh = g_Kh + headoff;
    const __nv_bfloat16* Kl = g_Kl + headoff;
    const __nv_bfloat16* Vh = g_Vh + headoff;
    const __nv_bfloat16* Vl = g_Vl + headoff;

    const int nk = 2 * (qt + 1);

    kv_prefetch(sb, 0, 0, Kh, Kl, Vh, Vl, tid);
    CP_COMMIT();

    // Q fragments (hi/lo), loaded straight from gmem in frag layout
    uint32_t qh[4][4], ql[4][4];
    {
        const size_t q0 = (size_t)(bb * Tn + qt * 128 + wp * 16 + g) * En
                        + hh * HSn;
        const size_t q1 = q0 + (size_t)8 * En;
        #pragma unroll
        for (int kk = 0; kk < 4; kk++) {
            const int c0 = kk * 16 + tg * 2, c1 = c0 + 8;
            qh[kk][0] = *(const uint32_t*)&g_Qh[q0 + c0];
            qh[kk][1] = *(const uint32_t*)&g_Qh[q1 + c0];
            qh[kk][2] = *(const uint32_t*)&g_Qh[q0 + c1];
            qh[kk][3] = *(const uint32_t*)&g_Qh[q1 + c1];
            ql[kk][0] = *(const uint32_t*)&g_Ql[q0 + c0];
            ql[kk][1] = *(const uint32_t*)&g_Ql[q1 + c0];
            ql[kk][2] = *(const uint32_t*)&g_Ql[q0 + c1];
            ql[kk][3] = *(const uint32_t*)&g_Ql[q1 + c1];
        }
    }

    float o[8][4];
    #pragma unroll
    for (int i = 0; i < 8; i++)
        #pragma unroll
        for (int e = 0; e < 4; e++) o[i][e] = 0.f;
    float m0 = -1e30f, m1 = -1e30f, l0 = 0.f, l1 = 0.f;
    const int qrow0 = qt * 128 + wp * 16 + g, qrow1 = qrow0 + 8;

    const uint32_t kboff = (((lane & 16) >> 1) + (lane & 7)) * 144
                         + ((lane & 8) ? 16 : 0);

    for (int kt = 0; kt < nk; kt++) {
        if (kt + 1 < nk) {
            kv_prefetch(sb, (kt + 1) & 1, kt + 1, Kh, Kl, Vh, Vl, tid);
            CP_COMMIT();
            CP_WAIT1();
        } else {
            CP_WAIT0();
        }
        __syncthreads();
        const uint32_t s0  = sb + (kt & 1) * KVSTAGE;
        const uint32_t kmh = s0, kml = s0 + KVTILE;
        const uint32_t vmh = s0 + 2 * KVTILE, vml = s0 + 3 * KVTILE;

        // ---- S = Q K^T (bf16x3), 8 n8-tiles of 64 keys
        float s[8][4];
        #pragma unroll
        for (int i = 0; i < 8; i++)
            #pragma unroll
            for (int e = 0; e < 4; e++) s[i][e] = 0.f;

        #pragma unroll
        for (int kk = 0; kk < 4; kk++) {
            uint32_t kbh[4][4], kbl[4][4];
            #pragma unroll
            for (int n4 = 0; n4 < 4; n4++) {
                const uint32_t r = n4 * 16 * 144 + kboff + kk * 32;
                ldsm_x4(kbh[n4], kmh + r);
                ldsm_x4(kbl[n4], kml + r);
            }
            #pragma unroll
            for (int nj = 0; nj < 8; nj++) {
                const uint32_t* bh_ = &kbh[nj >> 1][(nj & 1) * 2];
                const uint32_t* bl_ = &kbl[nj >> 1][(nj & 1) * 2];
                mma_bf16(s[nj], qh[kk], bh_);
                mma_bf16(s[nj], qh[kk], bl_);
                mma_bf16(s[nj], ql[kk], bh_);
            }
        }

        // ---- scale + causal mask
        const bool dm = (kt * 64 + 63) > qrow0;
        #pragma unroll
        for (int nj = 0; nj < 8; nj++)
            #pragma unroll
            for (int e = 0; e < 4; e++) {
                float v = s[nj][e] * 0.125f;
                if (dm) {
                    const int key = kt * 64 + nj * 8 + tg * 2 + (e & 1);
                    const int qr  = (e < 2) ? qrow0 : qrow1;
                    if (key > qr) v = -1e30f;
                }
                s[nj][e] = v;
            }

        // ---- online softmax (rows g and g+8)
        float mx0 = -1e30f, mx1 = -1e30f;
        #pragma unroll
        for (int nj = 0; nj < 8; nj++) {
            mx0 = fmaxf(mx0, fmaxf(s[nj][0], s[nj][1]));
            mx1 = fmaxf(mx1, fmaxf(s[nj][2], s[nj][3]));
        }
        mx0 = fmaxf(mx0, __shfl_xor_sync(0xffffffffu, mx0, 1));
        mx0 = fmaxf(mx0, __shfl_xor_sync(0xffffffffu, mx0, 2));
        mx1 = fmaxf(mx1, __shfl_xor_sync(0xffffffffu, mx1, 1));
        mx1 = fmaxf(mx1, __shfl_xor_sync(0xffffffffu, mx1, 2));
        const float mn0 = fmaxf(m0, mx0), mn1 = fmaxf(m1, mx1);
        const float a0 = __expf(m0 - mn0), a1 = __expf(m1 - mn1);
        m0 = mn0; m1 = mn1;
        float su0 = 0.f, su1 = 0.f;
        #pragma unroll
        for (int nj = 0; nj < 8; nj++) {
            s[nj][0] = __expf(s[nj][0] - mn0); su0 += s[nj][0];
            s[nj][1] = __expf(s[nj][1] - mn0); su0 += s[nj][1];
            s[nj][2] = __expf(s[nj][2] - mn1); su1 += s[nj][2];
            s[nj][3] = __expf(s[nj][3] - mn1); su1 += s[nj][3];
        }
        su0 += __shfl_xor_sync(0xffffffffu, su0, 1);
        su0 += __shfl_xor_sync(0xffffffffu, su0, 2);
        su1 += __shfl_xor_sync(0xffffffffu, su1, 1);
        su1 += __shfl_xor_sync(0xffffffffu, su1, 2);
        l0 = l0 * a0 + su0; l1 = l1 * a1 + su1;
        #pragma unroll
        for (int nj = 0; nj < 8; nj++) {
            o[nj][0] *= a0; o[nj][1] *= a0; o[nj][2] *= a1; o[nj][3] *= a1;
        }

        // ---- O += P V (P split hi/lo built per k16 of keys)
        #pragma unroll
        for (int kk = 0; kk < 4; kk++) {
            uint32_t pah[4], pal[4];
            {
                const float* p0 = s[2 * kk];
                const float* p1 = s[2 * kk + 1];
                __nv_bfloat16 h;
                float r0, r1;
                h = __float2bfloat16(p0[0]); r0 = p0[0] - __bfloat162float(h);
                float e0 = __bfloat162float(h);
                h = __float2bfloat16(p0[1]); r1 = p0[1] - __bfloat162float(h);
                pah[0] = packbf(e0, __bfloat162float(h));
                pal[0] = packbf(r0, r1);
                h = __float2bfloat16(p0[2]); r0 = p0[2] - __bfloat162float(h);
                e0 = __bfloat162float(h);
                h = __float2bfloat16(p0[3]); r1 = p0[3] - __bfloat162float(h);
                pah[1] = packbf(e0, __bfloat162float(h));
                pal[1] = packbf(r0, r1);
                h = __float2bfloat16(p1[0]); r0 = p1[0] - __bfloat162float(h);
                e0 = __bfloat162float(h);
                h = __float2bfloat16(p1[1]); r1 = p1[1] - __bfloat162float(h);
                pah[2] = packbf(e0, __bfloat162float(h));
                pal[2] = packbf(r0, r1);
                h = __float2bfloat16(p1[2]); r0 = p1[2] - __bfloat162float(h);
                e0 = __bfloat162float(h);
                h = __float2bfloat16(p1[3]); r1 = p1[3] - __bfloat162float(h);
                pah[3] = packbf(e0, __bfloat162float(h));
                pal[3] = packbf(r0, r1);
            }
            uint32_t vbh[4][4], vbl[4][4];
            const uint32_t voff = (kk * 16 + (lane & 15)) * 144
                                + ((lane & 16) ? 16 : 0);
            #pragma unroll
            for (int nb = 0; nb < 4; nb++) {
                ldsm_x4_t(vbh[nb], vmh + voff + nb * 32);
                ldsm_x4_t(vbl[nb], vml + voff + nb * 32);
            }
            #pragma unroll
            for (int nd = 0; nd < 8; nd++) {
                const uint32_t* bh_ = &vbh[nd >> 1][(nd & 1) * 2];
                const uint32_t* bl_ = &vbl[nd >> 1][(nd & 1) * 2];
                mma_bf16(o[nd], pah, bh_);
                mma_bf16(o[nd], pah, bl_);
                mma_bf16(o[nd], pal, bh_);
            }
        }
        __syncthreads();   // all reads of this KV buffer done before reuse
    }

    // ---- epilogue: normalize, bf16 hi/lo split into g_Ah / g_Al
    const float i0 = 1.f / l0, i1 = 1.f / l1;
    const size_t r0 = (size_t)(bb * Tn + qrow0) * En + hh * HSn;
    const size_t r1 = r0 + (size_t)8 * En;
    #pragma unroll
    for (int nd = 0; nd < 8; nd++) {
        const int col = nd * 8 + tg * 2;
        float v0 = o[nd][0] * i0, v1 = o[nd][1] * i0;
        float v2 = o[nd][2] * i1, v3 = o[nd][3] * i1;
        __nv_bfloat16 h0 = __float2bfloat16(v0), h1 = __float2bfloat16(v1);
        __nv_bfloat16 h2 = __float2bfloat16(v2), h3 = __float2bfloat16(v3);
        *(uint32_t*)&g_Ah[r0 + col] =
            packbf(__bfloat162float(h0), __bfloat162float(h1));
        *(uint32_t*)&g_Al[r0 + col] =
            packbf(v0 - __bfloat162float(h0), v1 - __bfloat162float(h1));
        *(uint32_t*)&g_Ah[r1 + col] =
            packbf(__bfloat162float(h2), __bfloat162float(h3));
        *(uint32_t*)&g_Al[r1 + col] =
            packbf(v2 - __bfloat162float(h2), v3 - __bfloat162float(h3));
    }
}

// =====================================================================
extern "C" void kernel_launch(void* const* d_in, const int* in_sizes, int n_in,
                              void* d_out, int out_size)
{
    (void)in_sizes; (void)n_in; (void)out_size;
    const float* X  = (const float*)d_in[0];
    const float* Wq = (const float*)d_in[1];
    const float* bq = (const float*)d_in[2];
    const float* Wk = (const float*)d_in[3];
    const float* bk = (const float*)d_in[4];
    const float* Wv = (const float*)d_in[5];
    const float* bv = (const float*)d_in[6];
    const float* Wo = (const float*)d_in[7];
    const float* bo = (const float*)d_in[8];
    float* out = (float*)d_out;

    cudaFuncSetAttribute(gemm_qkv,
                         cudaFuncAttributeMaxDynamicSharedMemorySize, GEMM_SMEM);
    cudaFuncSetAttribute(gemm_out,
                         cudaFuncAttributeMaxDynamicSharedMemorySize, GEMM_SMEM);
    cudaFuncSetAttribute(flash_mma,
                         cudaFuncAttributeMaxDynamicSharedMemorySize, FL_SMEM);

    dim3 blk(256);
    split_kernel<<<1024, 256>>>(X,  0, Mn * En);
    split_kernel<<<512,  256>>>(Wq, 1, En * En);
    split_kernel<<<512,  256>>>(Wk, 2, En * En);
    split_kernel<<<512,  256>>>(Wv, 3, En * En);
    split_kernel<<<512,  256>>>(Wo, 4, En * En);

    gemm_qkv<<<dim3(En / 128, Mn / 128, 3), blk, GEMM_SMEM>>>(bq, bk, bv);
    flash_mma<<<dim3(Tn / 128, Bn * NHn), blk, FL_SMEM>>>();
    gemm_out<<<dim3(En / 128, Mn / 128), blk, GEMM_SMEM>>>(bo, out);
}

// round 4
// speedup vs baseline: 2.6086x; 1.0624x over previous
#include <cuda_runtime.h>
#include <cuda_bf16.h>
#include <cstdint>

// Problem constants
#define Bn  2
#define Tn  2048
#define En  1024
#define NHn 16
#define HSn 64
#define Mn  (Bn * Tn)        // 4096 token rows

// ---------------- scratch (device globals; no allocation) ----------------
__device__ __nv_bfloat16 g_Xh[(size_t)Mn * En];
__device__ __nv_bfloat16 g_Xl[(size_t)Mn * En];
__device__ __nv_bfloat16 g_Wqh[(size_t)En * En];
__device__ __nv_bfloat16 g_Wql[(size_t)En * En];
__device__ __nv_bfloat16 g_Wkh[(size_t)En * En];
__device__ __nv_bfloat16 g_Wkl[(size_t)En * En];
__device__ __nv_bfloat16 g_Wvh[(size_t)En * En];
__device__ __nv_bfloat16 g_Wvl[(size_t)En * En];
__device__ __nv_bfloat16 g_Woh[(size_t)En * En];
__device__ __nv_bfloat16 g_Wol[(size_t)En * En];
__device__ __nv_bfloat16 g_Qh[(size_t)Mn * En];
__device__ __nv_bfloat16 g_Ql[(size_t)Mn * En];
__device__ __nv_bfloat16 g_Kh[(size_t)Mn * En];
__device__ __nv_bfloat16 g_Kl[(size_t)Mn * En];
__device__ __nv_bfloat16 g_Vh[(size_t)Mn * En];
__device__ __nv_bfloat16 g_Vl[(size_t)Mn * En];
__device__ __nv_bfloat16 g_Ah[(size_t)Mn * En];
__device__ __nv_bfloat16 g_Al[(size_t)Mn * En];

// =====================================================================
// Baseline-PTX helpers (valid on compute_103 virtual arch)
// =====================================================================
__device__ __forceinline__ uint32_t smem_u32(const void* p) {
    uint32_t a;
    asm("{ .reg .u64 t; cvta.to.shared.u64 t, %1; cvt.u32.u64 %0, t; }"
        : "=r"(a) : "l"(p));
    return a;
}

__device__ __forceinline__ void mma_bf16(float* d, const uint32_t* a,
                                         const uint32_t* b) {
    asm volatile(
        "mma.sync.aligned.m16n8k16.row.col.f32.bf16.bf16.f32 "
        "{%0,%1,%2,%3}, {%4,%5,%6,%7}, {%8,%9}, {%0,%1,%2,%3};\n"
        : "+f"(d[0]), "+f"(d[1]), "+f"(d[2]), "+f"(d[3])
        : "r"(a[0]), "r"(a[1]), "r"(a[2]), "r"(a[3]), "r"(b[0]), "r"(b[1]));
}

__device__ __forceinline__ void ldsm_x4(uint32_t* r, uint32_t a) {
    asm volatile("ldmatrix.sync.aligned.m8n8.x4.shared.b16 {%0,%1,%2,%3}, [%4];"
                 : "=r"(r[0]), "=r"(r[1]), "=r"(r[2]), "=r"(r[3]) : "r"(a));
}
__device__ __forceinline__ void ldsm_x4_t(uint32_t* r, uint32_t a) {
    asm volatile("ldmatrix.sync.aligned.m8n8.x4.trans.shared.b16 {%0,%1,%2,%3}, [%4];"
                 : "=r"(r[0]), "=r"(r[1]), "=r"(r[2]), "=r"(r[3]) : "r"(a));
}

__device__ __forceinline__ void cp16(uint32_t d, const void* g) {
    asm volatile("cp.async.cg.shared.global [%0], [%1], 16;" :: "r"(d), "l"(g));
}
#define CP_COMMIT() asm volatile("cp.async.commit_group;" ::: "memory")
#define CP_WAIT0()  asm volatile("cp.async.wait_group 0;" ::: "memory")
#define CP_WAIT1()  asm volatile("cp.async.wait_group 1;" ::: "memory")

__device__ __forceinline__ uint32_t packbf(float a, float b) {
    __nv_bfloat162 t = __floats2bfloat162_rn(a, b);   // .x = a -> low bits
    return *reinterpret_cast<uint32_t*>(&t);
}
__device__ __forceinline__ uint32_t pack2h(__nv_bfloat16 a, __nv_bfloat16 b) {
    __nv_bfloat162 t(a, b);
    return *reinterpret_cast<uint32_t*>(&t);
}

// =====================================================================
// Fused split kernel: one launch splits X + all 4 weights into bf16 hi/lo.
// float4-vectorized; segment boundaries are power-of-two aligned.
// X: 2^20 float4s; each weight: 2^18 float4s. Total 2^21 threads.
// =====================================================================
__global__ void __launch_bounds__(256) split_all(
    const float* __restrict__ X,  const float* __restrict__ Wq,
    const float* __restrict__ Wk, const float* __restrict__ Wv,
    const float* __restrict__ Wo)
{
    const int i = blockIdx.x * blockDim.x + threadIdx.x;   // float4 index
    const float* src; __nv_bfloat16 *hi, *lo; int base;
    if (i < (1 << 20)) {
        src = X; hi = g_Xh; lo = g_Xl; base = i;
    } else {
        const int r = i - (1 << 20);
        const int seg = r >> 18;
        base = r & ((1 << 18) - 1);
        switch (seg) {
            case 0:  src = Wq; hi = g_Wqh; lo = g_Wql; break;
            case 1:  src = Wk; hi = g_Wkh; lo = g_Wkl; break;
            case 2:  src = Wv; hi = g_Wvh; lo = g_Wvl; break;
            default: src = Wo; hi = g_Woh; lo = g_Wol; break;
        }
    }
    const float4 v = *(const float4*)(src + (size_t)base * 4);
    const __nv_bfloat16 h0 = __float2bfloat16(v.x), h1 = __float2bfloat16(v.y);
    const __nv_bfloat16 h2 = __float2bfloat16(v.z), h3 = __float2bfloat16(v.w);
    uint2 hh, ll;
    hh.x = pack2h(h0, h1);
    hh.y = pack2h(h2, h3);
    ll.x = packbf(v.x - __bfloat162float(h0), v.y - __bfloat162float(h1));
    ll.y = packbf(v.z - __bfloat162float(h2), v.w - __bfloat162float(h3));
    *(uint2*)(hi + (size_t)base * 4) = hh;
    *(uint2*)(lo + (size_t)base * 4) = ll;
}

// =====================================================================
// GEMM: C[128x128] = A[4096xK] * W^T + bias, bf16x3 via mma.sync.
// 256 thr, 8 warps (4m x 2n), k-stage 32, cp.async double buffer.
// smem row = 32 bf16 data + 8 pad = 80B (ldmatrix conflict-free).
// Split-MMA issued as 3 independent passes (hh, hl, lh) for ILP.
// =====================================================================
#define GTILE  (128 * 80)      // one [128 x 32] bf16 tile (padded)
#define GSTAGE (4 * GTILE)     // Ah, Al, Bh, Bl
#define GEMM_SMEM (2 * GSTAGE) // 81920

__device__ __forceinline__ void gemm_prefetch(
    uint32_t sbs, const __nv_bfloat16* pA0, const __nv_bfloat16* pA1,
    const __nv_bfloat16* pB0, const __nv_bfloat16* pB1, int k0, int tid)
{
    #pragma unroll
    for (int t = 0; t < 4; t++) {
        const __nv_bfloat16* s = (t == 0) ? pA0 : (t == 1) ? pA1
                               : (t == 2) ? pB0 : pB1;
        #pragma unroll
        for (int i = 0; i < 2; i++) {
            int cc  = i * 256 + tid;       // 0..511
            int row = cc >> 2, seg = cc & 3;
            cp16(sbs + t * GTILE + row * 80 + seg * 16,
                 s + (size_t)row * En + k0 + seg * 8);
        }
    }
}

__device__ __forceinline__ void gemm_core(
    const __nv_bfloat16* __restrict__ Ah, const __nv_bfloat16* __restrict__ Al,
    const __nv_bfloat16* __restrict__ Bh, const __nv_bfloat16* __restrict__ Bl,
    const float* __restrict__ bias, float* __restrict__ outF,
    __nv_bfloat16* __restrict__ outH, __nv_bfloat16* __restrict__ outL,
    float outScale)
{
    extern __shared__ char smc[];
    const uint32_t sb = smem_u32(smc);
    const int tid = threadIdx.x, lane = tid & 31, wid = tid >> 5;
    const int wm = wid & 3, wn = wid >> 2;
    const int rowBase = blockIdx.y * 128, colBase = blockIdx.x * 128;

    const __nv_bfloat16* pA0 = Ah + (size_t)rowBase * En;
    const __nv_bfloat16* pA1 = Al + (size_t)rowBase * En;
    const __nv_bfloat16* pB0 = Bh + (size_t)colBase * En;
    const __nv_bfloat16* pB1 = Bl + (size_t)colBase * En;

    float acc[2][8][4];
    #pragma unroll
    for (int i = 0; i < 2; i++)
        #pragma unroll
        for (int j = 0; j < 8; j++)
            #pragma unroll
            for (int e = 0; e < 4; e++) acc[i][j][e] = 0.f;

    gemm_prefetch(sb, pA0, pA1, pB0, pB1, 0, tid);
    CP_COMMIT();

    const uint32_t aoff = (lane & 15) * 80 + (lane >> 4) * 16;
    const uint32_t boff = (((lane & 16) >> 1) + (lane & 7)) * 80
                        + ((lane & 8) ? 16 : 0);

    for (int st = 0; st < En / 32; st++) {
        if (st + 1 < En / 32) {
            gemm_prefetch(sb + ((st + 1) & 1) * GSTAGE,
                          pA0, pA1, pB0, pB1, (st + 1) * 32, tid);
            CP_COMMIT();
            CP_WAIT1();
        } else {
            CP_WAIT0();
        }
        __syncthreads();
        const uint32_t s0 = sb + (st & 1) * GSTAGE;
        const uint32_t aH = s0, aL = s0 + GTILE, bH = s0 + 2 * GTILE,
                       bL = s0 + 3 * GTILE;

        #pragma unroll
        for (int kk = 0; kk < 2; kk++) {
            uint32_t ah[2][4], al[2][4], bh4[4][4], bl4[4][4];
            #pragma unroll
            for (int mi = 0; mi < 2; mi++) {
                const uint32_t r = (wm * 32 + mi * 16) * 80 + aoff + kk * 32;
                ldsm_x4(ah[mi], aH + r);
                ldsm_x4(al[mi], aL + r);
            }
            #pragma unroll
            for (int n4 = 0; n4 < 4; n4++) {
                const uint32_t r = (wn * 64 + n4 * 16) * 80 + boff + kk * 32;
                ldsm_x4(bh4[n4], bH + r);
                ldsm_x4(bl4[n4], bL + r);
            }
            // 3 independent passes: 16 independent acc chains per pass
            #pragma unroll
            for (int mi = 0; mi < 2; mi++)
                #pragma unroll
                for (int nj = 0; nj < 8; nj++)
                    mma_bf16(acc[mi][nj], ah[mi], &bh4[nj >> 1][(nj & 1) * 2]);
            #pragma unroll
            for (int mi = 0; mi < 2; mi++)
                #pragma unroll
                for (int nj = 0; nj < 8; nj++)
                    mma_bf16(acc[mi][nj], ah[mi], &bl4[nj >> 1][(nj & 1) * 2]);
            #pragma unroll
            for (int mi = 0; mi < 2; mi++)
                #pragma unroll
                for (int nj = 0; nj < 8; nj++)
                    mma_bf16(acc[mi][nj], al[mi], &bh4[nj >> 1][(nj & 1) * 2]);
        }
        __syncthreads();
    }

    // epilogue
    #pragma unroll
    for (int mi = 0; mi < 2; mi++) {
        const int rb = rowBase + wm * 32 + mi * 16 + (lane >> 2);
        #pragma unroll
        for (int half = 0; half < 2; half++) {
            const size_t r = (size_t)(rb + half * 8);
            #pragma unroll
            for (int nj = 0; nj < 8; nj++) {
                const int col = colBase + wn * 64 + nj * 8 + (lane & 3) * 2;
                float v0 = (acc[mi][nj][half * 2 + 0] + bias[col]) * outScale;
                float v1 = (acc[mi][nj][half * 2 + 1] + bias[col + 1]) * outScale;
                if (outF) {
                    *(float2*)&outF[r * En + col] = make_float2(v0, v1);
                } else {
                    __nv_bfloat16 h0 = __float2bfloat16(v0);
                    __nv_bfloat16 h1 = __float2bfloat16(v1);
                    *(uint32_t*)&outH[r * En + col] = pack2h(h0, h1);
                    *(uint32_t*)&outL[r * En + col] =
                        packbf(v0 - __bfloat162float(h0),
                               v1 - __bfloat162float(h1));
                }
            }
        }
    }
}

__global__ void __launch_bounds__(256) gemm_qkv(
    const float* bq, const float* bk, const float* bv)
{
    const __nv_bfloat16 *Wh, *Wl; const float* bias;
    __nv_bfloat16 *oh, *ol; float sc;
    if (blockIdx.z == 0)      { Wh = g_Wqh; Wl = g_Wql; bias = bq;
                                oh = g_Qh; ol = g_Ql; sc = 0.125f; }
    else if (blockIdx.z == 1) { Wh = g_Wkh; Wl = g_Wkl; bias = bk;
                                oh = g_Kh; ol = g_Kl; sc = 1.0f; }
    else                      { Wh = g_Wvh; Wl = g_Wvl; bias = bv;
                                oh = g_Vh; ol = g_Vl; sc = 1.0f; }
    gemm_core(g_Xh, g_Xl, Wh, Wl, bias, nullptr, oh, ol, sc);
}

__global__ void __launch_bounds__(256) gemm_out(const float* bo, float* out)
{
    gemm_core(g_Ah, g_Al, g_Woh, g_Wol, bo, out, nullptr, nullptr, 1.0f);
}

// =====================================================================
// Flash attention (causal) via mma.sync bf16x3. Q pre-scaled by 1/8.
// CTA: 128 q rows x 64-key tiles, 256 thr, warp w owns rows w*16..+15.
// KV tiles (Kh,Kl,Vh,Vl) [64 x 64] bf16, smem row 64+8 pad = 144B.
// =====================================================================
#define KVTILE  (64 * 144)     // 9216
#define KVSTAGE (4 * KVTILE)   // 36864
#define FL_SMEM (2 * KVSTAGE)  // 73728

__device__ __forceinline__ void kv_prefetch(
    uint32_t sb, int buf, int kt2,
    const __nv_bfloat16* Kh, const __nv_bfloat16* Kl,
    const __nv_bfloat16* Vh, const __nv_bfloat16* Vl, int tid)
{
    const uint32_t s0 = sb + buf * KVSTAGE;
    const size_t rowoff = (size_t)kt2 * 64;
    #pragma unroll
    for (int t = 0; t < 4; t++) {
        const __nv_bfloat16* src = (t == 0) ? Kh : (t == 1) ? Kl
                                 : (t == 2) ? Vh : Vl;
        #pragma unroll
        for (int i = 0; i < 2; i++) {
            int cc  = i * 256 + tid;     // 0..511
            int row = cc >> 3, seg = cc & 7;
            cp16(s0 + t * KVTILE + row * 144 + seg * 16,
                 src + (rowoff + row) * En + seg * 8);
        }
    }
}

__global__ void __launch_bounds__(256) flash_mma()
{
    extern __shared__ char smc[];
    const uint32_t sb = smem_u32(smc);
    const int tid = threadIdx.x, lane = tid & 31, wp = tid >> 5;
    const int g = lane >> 2, tg = lane & 3;
    const int qt = (int)gridDim.x - 1 - (int)blockIdx.x;   // big tiles first
    const int bh = blockIdx.y, bb = bh >> 4, hh = bh & 15;

    const size_t headoff = (size_t)bb * Tn * En + hh * HSn;
    const __nv_bfloat16* Kh = g_Kh + headoff;
    const __nv_bfloat16* Kl = g_Kl + headoff;
    const __nv_bfloat16* Vh = g_Vh + headoff;
    const __nv_bfloat16* Vl = g_Vl + headoff;

    const int nk = 2 * (qt + 1);

    kv_prefetch(sb, 0, 0, Kh, Kl, Vh, Vl, tid);
    CP_COMMIT();

    // Q fragments (hi/lo), loaded straight from gmem in frag layout
    uint32_t qh[4][4], ql[4][4];
    {
        const size_t q0 = (size_t)(bb * Tn + qt * 128 + wp * 16 + g) * En
                        + hh * HSn;
        const size_t q1 = q0 + (size_t)8 * En;
        #pragma unroll
        for (int kk = 0; kk < 4; kk++) {
            const int c0 = kk * 16 + tg * 2, c1 = c0 + 8;
            qh[kk][0] = *(const uint32_t*)&g_Qh[q0 + c0];
            qh[kk][1] = *(const uint32_t*)&g_Qh[q1 + c0];
            qh[kk][2] = *(const uint32_t*)&g_Qh[q0 + c1];
            qh[kk][3] = *(const uint32_t*)&g_Qh[q1 + c1];
            ql[kk][0] = *(const uint32_t*)&g_Ql[q0 + c0];
            ql[kk][1] = *(const uint32_t*)&g_Ql[q1 + c0];
            ql[kk][2] = *(const uint32_t*)&g_Ql[q0 + c1];
            ql[kk][3] = *(const uint32_t*)&g_Ql[q1 + c1];
        }
    }

    float o[8][4];
    #pragma unroll
    for (int i = 0; i < 8; i++)
        #pragma unroll
        for (int e = 0; e < 4; e++) o[i][e] = 0.f;
    float m0 = -1e30f, m1 = -1e30f, l0 = 0.f, l1 = 0.f;
    const int qrow0 = qt * 128 + wp * 16 + g, qrow1 = qrow0 + 8;

    const uint32_t kboff = (((lane & 16) >> 1) + (lane & 7)) * 144
                         + ((lane & 8) ? 16 : 0);

    for (int kt = 0; kt < nk; kt++) {
        if (kt + 1 < nk) {
            kv_prefetch(sb, (kt + 1) & 1, kt + 1, Kh, Kl, Vh, Vl, tid);
            CP_COMMIT();
            CP_WAIT1();
        } else {
            CP_WAIT0();
        }
        __syncthreads();
        const uint32_t s0  = sb + (kt & 1) * KVSTAGE;
        const uint32_t kmh = s0, kml = s0 + KVTILE;
        const uint32_t vmh = s0 + 2 * KVTILE, vml = s0 + 3 * KVTILE;

        // ---- S = Q K^T (bf16x3; Q pre-scaled), 8 n8-tiles of 64 keys
        float s[8][4];
        #pragma unroll
        for (int i = 0; i < 8; i++)
            #pragma unroll
            for (int e = 0; e < 4; e++) s[i][e] = 0.f;

        #pragma unroll
        for (int kk = 0; kk < 4; kk++) {
            uint32_t kbh[4][4], kbl[4][4];
            #pragma unroll
            for (int n4 = 0; n4 < 4; n4++) {
                const uint32_t r = n4 * 16 * 144 + kboff + kk * 32;
                ldsm_x4(kbh[n4], kmh + r);
                ldsm_x4(kbl[n4], kml + r);
            }
            #pragma unroll
            for (int nj = 0; nj < 8; nj++)
                mma_bf16(s[nj], qh[kk], &kbh[nj >> 1][(nj & 1) * 2]);
            #pragma unroll
            for (int nj = 0; nj < 8; nj++)
                mma_bf16(s[nj], qh[kk], &kbl[nj >> 1][(nj & 1) * 2]);
            #pragma unroll
            for (int nj = 0; nj < 8; nj++)
                mma_bf16(s[nj], ql[kk], &kbh[nj >> 1][(nj & 1) * 2]);
        }

        // ---- causal mask (diagonal tiles only; no scaling needed)
        if (kt * 64 + 63 > qrow0) {
            #pragma unroll
            for (int nj = 0; nj < 8; nj++)
                #pragma unroll
                for (int e = 0; e < 4; e++) {
                    const int key = kt * 64 + nj * 8 + tg * 2 + (e & 1);
                    const int qr  = (e < 2) ? qrow0 : qrow1;
                    if (key > qr) s[nj][e] = -1e30f;
                }
        }

        // ---- online softmax (rows g and g+8)
        float mx0 = -1e30f, mx1 = -1e30f;
        #pragma unroll
        for (int nj = 0; nj < 8; nj++) {
            mx0 = fmaxf(mx0, fmaxf(s[nj][0], s[nj][1]));
            mx1 = fmaxf(mx1, fmaxf(s[nj][2], s[nj][3]));
        }
        mx0 = fmaxf(mx0, __shfl_xor_sync(0xffffffffu, mx0, 1));
        mx0 = fmaxf(mx0, __shfl_xor_sync(0xffffffffu, mx0, 2));
        mx1 = fmaxf(mx1, __shfl_xor_sync(0xffffffffu, mx1, 1));
        mx1 = fmaxf(mx1, __shfl_xor_sync(0xffffffffu, mx1, 2));
        const float mn0 = fmaxf(m0, mx0), mn1 = fmaxf(m1, mx1);
        const float a0 = __expf(m0 - mn0), a1 = __expf(m1 - mn1);
        m0 = mn0; m1 = mn1;
        float su0 = 0.f, su1 = 0.f;
        #pragma unroll
        for (int nj = 0; nj < 8; nj++) {
            s[nj][0] = __expf(s[nj][0] - mn0); su0 += s[nj][0];
            s[nj][1] = __expf(s[nj][1] - mn0); su0 += s[nj][1];
            s[nj][2] = __expf(s[nj][2] - mn1); su1 += s[nj][2];
            s[nj][3] = __expf(s[nj][3] - mn1); su1 += s[nj][3];
        }
        su0 += __shfl_xor_sync(0xffffffffu, su0, 1);
        su0 += __shfl_xor_sync(0xffffffffu, su0, 2);
        su1 += __shfl_xor_sync(0xffffffffu, su1, 1);
        su1 += __shfl_xor_sync(0xffffffffu, su1, 2);
        l0 = l0 * a0 + su0; l1 = l1 * a1 + su1;
        #pragma unroll
        for (int nj = 0; nj < 8; nj++) {
            o[nj][0] *= a0; o[nj][1] *= a0; o[nj][2] *= a1; o[nj][3] *= a1;
        }

        // ---- O += P V (P split hi/lo built per k16 of keys)
        #pragma unroll
        for (int kk = 0; kk < 4; kk++) {
            uint32_t pah[4], pal[4];
            {
                const float* p0 = s[2 * kk];
                const float* p1 = s[2 * kk + 1];
                __nv_bfloat16 h;
                float r0, r1;
                h = __float2bfloat16(p0[0]); r0 = p0[0] - __bfloat162float(h);
                float e0 = __bfloat162float(h);
                h = __float2bfloat16(p0[1]); r1 = p0[1] - __bfloat162float(h);
                pah[0] = packbf(e0, __bfloat162float(h));
                pal[0] = packbf(r0, r1);
                h = __float2bfloat16(p0[2]); r0 = p0[2] - __bfloat162float(h);
                e0 = __bfloat162float(h);
                h = __float2bfloat16(p0[3]); r1 = p0[3] - __bfloat162float(h);
                pah[1] = packbf(e0, __bfloat162float(h));
                pal[1] = packbf(r0, r1);
                h = __float2bfloat16(p1[0]); r0 = p1[0] - __bfloat162float(h);
                e0 = __bfloat162float(h);
                h = __float2bfloat16(p1[1]); r1 = p1[1] - __bfloat162float(h);
                pah[2] = packbf(e0, __bfloat162float(h));
                pal[2] = packbf(r0, r1);
                h = __float2bfloat16(p1[2]); r0 = p1[2] - __bfloat162float(h);
                e0 = __bfloat162float(h);
                h = __float2bfloat16(p1[3]); r1 = p1[3] - __bfloat162float(h);
                pah[3] = packbf(e0, __bfloat162float(h));
                pal[3] = packbf(r0, r1);
            }
            uint32_t vbh[4][4], vbl[4][4];
            const uint32_t voff = (kk * 16 + (lane & 15)) * 144
                                + ((lane & 16) ? 16 : 0);
            #pragma unroll
            for (int nb = 0; nb < 4; nb++) {
                ldsm_x4_t(vbh[nb], vmh + voff + nb * 32);
                ldsm_x4_t(vbl[nb], vml + voff + nb * 32);
            }
            #pragma unroll
            for (int nd = 0; nd < 8; nd++)
                mma_bf16(o[nd], pah, &vbh[nd >> 1][(nd & 1) * 2]);
            #pragma unroll
            for (int nd = 0; nd < 8; nd++)
                mma_bf16(o[nd], pah, &vbl[nd >> 1][(nd & 1) * 2]);
            #pragma unroll
            for (int nd = 0; nd < 8; nd++)
                mma_bf16(o[nd], pal, &vbh[nd >> 1][(nd & 1) * 2]);
        }
        __syncthreads();   // all reads of this KV buffer done before reuse
    }

    // ---- epilogue: normalize, bf16 hi/lo split into g_Ah / g_Al
    const float i0 = 1.f / l0, i1 = 1.f / l1;
    const size_t r0 = (size_t)(bb * Tn + qrow0) * En + hh * HSn;
    const size_t r1 = r0 + (size_t)8 * En;
    #pragma unroll
    for (int nd = 0; nd < 8; nd++) {
        const int col = nd * 8 + tg * 2;
        float v0 = o[nd][0] * i0, v1 = o[nd][1] * i0;
        float v2 = o[nd][2] * i1, v3 = o[nd][3] * i1;
        __nv_bfloat16 h0 = __float2bfloat16(v0), h1 = __float2bfloat16(v1);
        __nv_bfloat16 h2 = __float2bfloat16(v2), h3 = __float2bfloat16(v3);
        *(uint32_t*)&g_Ah[r0 + col] = pack2h(h0, h1);
        *(uint32_t*)&g_Al[r0 + col] =
            packbf(v0 - __bfloat162float(h0), v1 - __bfloat162float(h1));
        *(uint32_t*)&g_Ah[r1 + col] = pack2h(h2, h3);
        *(uint32_t*)&g_Al[r1 + col] =
            packbf(v2 - __bfloat162float(h2), v3 - __bfloat162float(h3));
    }
}

// =====================================================================
extern "C" void kernel_launch(void* const* d_in, const int* in_sizes, int n_in,
                              void* d_out, int out_size)
{
    (void)in_sizes; (void)n_in; (void)out_size;
    const float* X  = (const float*)d_in[0];
    const float* Wq = (const float*)d_in[1];
    const float* bq = (const float*)d_in[2];
    const float* Wk = (const float*)d_in[3];
    const float* bk = (const float*)d_in[4];
    const float* Wv = (const float*)d_in[5];
    const float* bv = (const float*)d_in[6];
    const float* Wo = (const float*)d_in[7];
    const float* bo = (const float*)d_in[8];
    float* out = (float*)d_out;

    cudaFuncSetAttribute(gemm_qkv,
                         cudaFuncAttributeMaxDynamicSharedMemorySize, GEMM_SMEM);
    cudaFuncSetAttribute(gemm_out,
                         cudaFuncAttributeMaxDynamicSharedMemorySize, GEMM_SMEM);
    cudaFuncSetAttribute(flash_mma,
                         cudaFuncAttributeMaxDynamicSharedMemorySize, FL_SMEM);

    dim3 blk(256);
    split_all<<<8192, 256>>>(X, Wq, Wk, Wv, Wo);
    gemm_qkv<<<dim3(En / 128, Mn / 128, 3), blk, GEMM_SMEM>>>(bq, bk, bv);
    flash_mma<<<dim3(Tn / 128, Bn * NHn), blk, FL_SMEM>>>();
    gemm_out<<<dim3(En / 128, Mn / 128), blk, GEMM_SMEM>>>(bo, out);
}